// round 9
// baseline (speedup 1.0000x reference)
#include <cuda_runtime.h>
#include <math.h>
#include <float.h>
#include <stdint.h>

#define BATCH 2
#define NPTS  4096
#define DIM   128
#define MD    16
#define KNBR  32
#define EDIM  530              // 2*EDGE_IN
#define EDIMP 544              // padded to 17*32
#define NROWS (BATCH*NPTS)     // 8192

// ---------------- scratch (device globals; zero-initialized at load) ----------------
__device__ float g_G [NROWS*EDIMP];   // padded cols stay zero (never written)
__device__ float g_H [NROWS*EDIMP];
__device__ float g_mi[NROWS*MD];
__device__ float g_Hn[NROWS*(2*DIM)];
__device__ float g_knn_dist[NROWS*KNBR];
__device__ int   g_knn_idx [NROWS*KNBR];

// fast SiLU: MUFU.EX2 + MUFU.RCP, rel err ~1e-6 (threshold is 1e-3)
__device__ __forceinline__ float silu_f(float x){
    return __fdividef(x, 1.0f + __expf(-x));
}

// ---------------- kernel 1: exact KNN ----------------
__global__ __launch_bounds__(256) void knn_kernel(const float* __restrict__ coors)
{
    __shared__ unsigned long long ck[256];
    const int b = blockIdx.y, i = blockIdx.x, tid = threadIdx.x;
    const int lane = tid & 31, w = tid >> 5;
    const float* cb = coors + (size_t)b*NPTS*3;
    const float cx = cb[i*3+0], cy = cb[i*3+1], cz = cb[i*3+2];

    float dl[16];
    const int jbase = w*512 + lane;
    #pragma unroll
    for (int t = 0; t < 16; t++) {
        int j = jbase + t*32;
        float dx = cx - cb[j*3+0];
        float dy = cy - cb[j*3+1];
        float dz = cz - cb[j*3+2];
        dl[t] = __fadd_rn(__fadd_rn(__fmul_rn(dx,dx), __fmul_rn(dy,dy)), __fmul_rn(dz,dz));
    }

    for (int k = 0; k < KNBR; k++) {
        float best = FLT_MAX; int bt = 0;
        #pragma unroll
        for (int t = 0; t < 16; t++)
            if (dl[t] < best) { best = dl[t]; bt = t; }
        int bj = jbase + bt*32;
        float v = best; int jj = (best < FLT_MAX) ? bj : 0x7fffffff;
        #pragma unroll
        for (int off = 16; off > 0; off >>= 1) {
            float v2 = __shfl_xor_sync(0xffffffffu, v, off);
            int   j2 = __shfl_xor_sync(0xffffffffu, jj, off);
            if (v2 < v || (v2 == v && j2 < jj)) { v = v2; jj = j2; }
        }
        if (jj == bj) dl[bt] = FLT_MAX;
        if (lane == 0)
            ck[w*32 + k] = ((unsigned long long)__float_as_uint(v) << 32) | (unsigned int)jj;
    }
    __syncthreads();

    // bitonic sort 256 keys ascending
    #pragma unroll 1
    for (int k = 2; k <= 256; k <<= 1) {
        #pragma unroll 1
        for (int j = k >> 1; j > 0; j >>= 1) {
            int p = tid ^ j;
            if (p > tid) {
                bool asc = ((tid & k) == 0);
                unsigned long long a = ck[tid], bb = ck[p];
                if ((a > bb) == asc) { ck[tid] = bb; ck[p] = a; }
            }
            __syncthreads();
        }
    }
    if (tid < KNBR) {
        unsigned long long key = ck[tid];
        const int gi = b*NPTS + i;
        g_knn_dist[gi*KNBR + tid] = __uint_as_float((unsigned int)(key >> 32));
        g_knn_idx [gi*KNBR + tid] = (int)(unsigned int)(key & 0xffffffffu);
    }
}

// ---------------- generic tiled SGEMM: C = act(A@B + bias) (+resid), ldc ----------------
__global__ __launch_bounds__(256) void sgemm_kernel(
    const float* __restrict__ A, const float* __restrict__ B,
    const float* __restrict__ bias, const float* __restrict__ resid,
    float* __restrict__ C, int M, int N, int K, int act, int ldc)
{
    __shared__ float As[16][65];
    __shared__ float Bs[16][68];
    const int tid = threadIdx.x;
    const int tx = tid & 15, ty = tid >> 4;
    const int rowBase = blockIdx.y * 64, colBase = blockIdx.x * 64;
    const int aK = tid & 15, aRow = tid >> 4;
    const int bCol = tid & 63, bK = tid >> 6;
    float acc[4][4] = {};

    for (int k0 = 0; k0 < K; k0 += 16) {
        #pragma unroll
        for (int s = 0; s < 4; s++) {
            int r = aRow + s*16;
            As[aK][r] = A[(size_t)(rowBase + r)*K + k0 + aK];
        }
        #pragma unroll
        for (int s = 0; s < 4; s++) {
            int kk = bK + s*4;
            int col = colBase + bCol;
            Bs[kk][bCol] = (col < N) ? B[(size_t)(k0 + kk)*N + col] : 0.0f;
        }
        __syncthreads();
        #pragma unroll
        for (int kk = 0; kk < 16; kk++) {
            float a[4], bb[4];
            #pragma unroll
            for (int i = 0; i < 4; i++) a[i] = As[kk][ty*4 + i];
            #pragma unroll
            for (int j = 0; j < 4; j++) bb[j] = Bs[kk][tx*4 + j];
            #pragma unroll
            for (int i = 0; i < 4; i++)
                #pragma unroll
                for (int j = 0; j < 4; j++)
                    acc[i][j] = fmaf(a[i], bb[j], acc[i][j]);
        }
        __syncthreads();
    }
    #pragma unroll
    for (int i = 0; i < 4; i++) {
        int r = rowBase + ty*4 + i;
        #pragma unroll
        for (int j = 0; j < 4; j++) {
            int col = colBase + tx*4 + j;
            if (col < N) {
                float v = acc[i][j];
                if (bias)  v += bias[col];
                if (act)   v = silu_f(v);
                if (resid) v += resid[(size_t)r*N + col];
                C[(size_t)r*ldc + col] = v;
            }
        }
    }
}

// ------- node-MLP layer 1 GEMM with A = [feats | m_i] fused (K = 144) -------
__global__ __launch_bounds__(256) void gemm_node1(
    const float* __restrict__ feats, const float* __restrict__ B,
    const float* __restrict__ bias, float* __restrict__ C, int N)
{
    const int K = DIM + MD;
    __shared__ float As[16][65];
    __shared__ float Bs[16][68];
    const int tid = threadIdx.x;
    const int tx = tid & 15, ty = tid >> 4;
    const int rowBase = blockIdx.y * 64, colBase = blockIdx.x * 64;
    const int aK = tid & 15, aRow = tid >> 4;
    const int bCol = tid & 63, bK = tid >> 6;
    float acc[4][4] = {};

    for (int k0 = 0; k0 < K; k0 += 16) {
        #pragma unroll
        for (int s = 0; s < 4; s++) {
            int r = rowBase + aRow + s*16;
            int kk = k0 + aK;
            As[aK][aRow + s*16] = (kk < DIM) ? feats[(size_t)r*DIM + kk]
                                             : g_mi[(size_t)r*MD + (kk - DIM)];
        }
        #pragma unroll
        for (int s = 0; s < 4; s++) {
            int kk = bK + s*4;
            int col = colBase + bCol;
            Bs[kk][bCol] = B[(size_t)(k0 + kk)*N + col];
        }
        __syncthreads();
        #pragma unroll
        for (int kk = 0; kk < 16; kk++) {
            float a[4], bb[4];
            #pragma unroll
            for (int i = 0; i < 4; i++) a[i] = As[kk][ty*4 + i];
            #pragma unroll
            for (int j = 0; j < 4; j++) bb[j] = Bs[kk][tx*4 + j];
            #pragma unroll
            for (int i = 0; i < 4; i++)
                #pragma unroll
                for (int j = 0; j < 4; j++)
                    acc[i][j] = fmaf(a[i], bb[j], acc[i][j]);
        }
        __syncthreads();
    }
    #pragma unroll
    for (int i = 0; i < 4; i++) {
        int r = rowBase + ty*4 + i;
        #pragma unroll
        for (int j = 0; j < 4; j++) {
            int col = colBase + tx*4 + j;
            float v = acc[i][j] + bias[col];
            C[(size_t)r*N + col] = silu_f(v);
        }
    }
}

// ---------------- edge kernel: 8 warps, 1 node/warp, lane = edge ----------------
#define SM_W2    0
#define SM_WF    (16*EDIMP)
#define SM_WC1   (25*EDIMP)
#define SM_BC1   (SM_WC1 + 1024)
#define SM_WC2   (SM_BC1 + 64)
#define SM_BE2   (SM_WC2 + 64)
#define SM_HS    (SM_BE2 + 16)
#define HS_PITCH 36                     // 32 cols + 4 pad
#define HS_WARP  (32*HS_PITCH)          // 1 node x 32 rows x 36
#define SM_TOTAL_FLOATS (SM_HS + 8*HS_WARP)
#define EDGE_SMEM_BYTES (SM_TOTAL_FLOATS * 4)

__global__ __launch_bounds__(256, 2) void edge_kernel(
    const float* __restrict__ coors,
    const float* __restrict__ We2,  const float* __restrict__ be2,
    const float* __restrict__ Wc1,  const float* __restrict__ bc1,
    const float* __restrict__ Wc2,  const float* __restrict__ bc2,
    const float* __restrict__ We1,
    float* __restrict__ out_coors)
{
    extern __shared__ float sm[];
    float* sW2  = sm + SM_W2;    // [16][544]
    float* sWf  = sm + SM_WF;    // [9][544]
    float* sWc1 = sm + SM_WC1;   // [16][64]
    float* sBc1 = sm + SM_BC1;
    float* sWc2 = sm + SM_WC2;
    float* sBe2 = sm + SM_BE2;

    const int tid = threadIdx.x, lane = tid & 31, w = tid >> 5;
    const int b = blockIdx.y;
    const int i = blockIdx.x * 8 + w;
    const int gi = b*NPTS + i;

    // cooperative weight staging (256 threads)
    for (int t = tid; t < 16*EDIMP; t += 256) {
        int m = t / EDIMP, x = t % EDIMP;
        sW2[t] = (x < EDIM) ? We2[x*16 + m] : 0.0f;
    }
    for (int t = tid; t < 9*EDIMP; t += 256) {
        int r = t / EDIMP, x = t % EDIMP;
        sWf[t] = (x < EDIM) ? We1[(256 + r)*EDIM + x] : 0.0f;
    }
    for (int t = tid; t < 1024; t += 256) sWc1[t] = Wc1[t];
    if (tid < 64) { sBc1[tid] = bc1[tid]; sWc2[tid] = Wc2[tid]; }
    if (tid < 16) sBe2[tid] = be2[tid];
    __syncthreads();

    const float bc2v = bc2[0];

    // this lane's edge
    const int   j = g_knn_idx [gi*KNBR + lane];
    const float d = g_knn_dist[gi*KNBR + lane];
    float f[9];
    {
        const float invs[4] = {1.0f, 0.5f, 0.25f, 0.125f};
        #pragma unroll
        for (int r = 0; r < 4; r++) {
            float sv, cv;
            sincosf(d * invs[r], &sv, &cv);
            f[r] = sv; f[4+r] = cv;
        }
        f[8] = d;
    }

    const float* Hb = g_H + (size_t)b*NPTS*EDIMP;
    const float* Gp = g_G + (size_t)gi*EDIMP;
    float* hs = sm + SM_HS + w*HS_WARP;    // [32][36]

    float acc[16] = {};

    const int rr = (lane >> 3);          // row sub-index within 4-row group
    const int cc = (lane & 7) * 4;       // float col offset within chunk

    #pragma unroll 1
    for (int ch = 0; ch < 17; ch++) {
        const int c0 = ch * 32;
        __syncwarp();
        // coalesced staging: instr i loads rows 4i..4i+3, 8 lanes per 128B line
        #pragma unroll
        for (int i2 = 0; i2 < 8; i2++) {
            int row = i2*4 + rr;
            int jr = __shfl_sync(0xffffffffu, j, row);
            float4 v = __ldg((const float4*)(Hb + (size_t)jr*EDIMP + c0 + cc));
            *(float4*)&hs[row*HS_PITCH + cc] = v;
        }
        __syncwarp();
        #pragma unroll
        for (int xs = 0; xs < 8; xs++) {
            const int x = c0 + xs*4;
            float4 g4 = __ldg((const float4*)(Gp + x));       // broadcast
            float4 h4 = *(const float4*)&hs[lane*HS_PITCH + xs*4];
            float t0 = g4.x + h4.x, t1 = g4.y + h4.y, t2 = g4.z + h4.z, t3 = g4.w + h4.w;
            #pragma unroll
            for (int r = 0; r < 9; r++) {
                float4 wf = *(const float4*)&sWf[r*EDIMP + x]; // broadcast LDS
                t0 = fmaf(f[r], wf.x, t0); t1 = fmaf(f[r], wf.y, t1);
                t2 = fmaf(f[r], wf.z, t2); t3 = fmaf(f[r], wf.w, t3);
            }
            float s0 = silu_f(t0), s1 = silu_f(t1), s2 = silu_f(t2), s3 = silu_f(t3);
            #pragma unroll
            for (int m = 0; m < 16; m++) {
                float4 wm = *(const float4*)&sW2[m*EDIMP + x]; // broadcast LDS
                acc[m] = fmaf(s0, wm.x, fmaf(s1, wm.y, fmaf(s2, wm.z, fmaf(s3, wm.w, acc[m]))));
            }
        }
    }

    // ---------------- epilogue ----------------
    float mij[16];
    #pragma unroll
    for (int m = 0; m < 16; m++) mij[m] = silu_f(acc[m] + sBe2[m]);

    // m_i = sum over lanes; lane m writes component m
    #pragma unroll
    for (int m = 0; m < 16; m++) {
        float v = mij[m];
        #pragma unroll
        for (int off = 16; off > 0; off >>= 1)
            v += __shfl_xor_sync(0xffffffffu, v, off);
        if (lane == m) g_mi[(size_t)gi*MD + m] = v;
    }

    // coors MLP per edge: 16 -> 64 (silu) -> 1
    float cw = 0.0f;
    #pragma unroll 4
    for (int hh = 0; hh < 64; hh++) {
        float v = sBc1[hh];
        #pragma unroll
        for (int m = 0; m < 16; m++)
            v = fmaf(mij[m], sWc1[m*64 + hh], v);
        cw = fmaf(silu_f(v), sWc2[hh], cw);
    }
    cw += bc2v;

    // coors_out = sum_e cw_e * (c_i - c_je) + c_i
    {
        const float ci0 = coors[(size_t)gi*3+0];
        const float ci1 = coors[(size_t)gi*3+1];
        const float ci2 = coors[(size_t)gi*3+2];
        const float* cj = coors + ((size_t)b*NPTS + j)*3;
        float rx = cw * (ci0 - cj[0]);
        float ry = cw * (ci1 - cj[1]);
        float rz = cw * (ci2 - cj[2]);
        #pragma unroll
        for (int off = 16; off > 0; off >>= 1) {
            rx += __shfl_xor_sync(0xffffffffu, rx, off);
            ry += __shfl_xor_sync(0xffffffffu, ry, off);
            rz += __shfl_xor_sync(0xffffffffu, rz, off);
        }
        if (lane == 0) {
            out_coors[(size_t)gi*3+0] = rx + ci0;
            out_coors[(size_t)gi*3+1] = ry + ci1;
            out_coors[(size_t)gi*3+2] = rz + ci2;
        }
    }
}

// ---------------- host launcher ----------------
extern "C" void kernel_launch(void* const* d_in, const int* in_sizes, int n_in,
                              void* d_out, int out_size)
{
    const float* feats = (const float*)d_in[0];
    const float* coors = (const float*)d_in[1];
    const float* We1   = (const float*)d_in[2];
    const float* be1   = (const float*)d_in[3];
    const float* We2   = (const float*)d_in[4];
    const float* be2   = (const float*)d_in[5];
    const float* Wc1   = (const float*)d_in[6];
    const float* bc1   = (const float*)d_in[7];
    const float* Wc2   = (const float*)d_in[8];
    const float* bc2   = (const float*)d_in[9];
    const float* Wn1   = (const float*)d_in[10];
    const float* bn1   = (const float*)d_in[11];
    const float* Wn2   = (const float*)d_in[12];
    const float* bn2   = (const float*)d_in[13];

    float* out       = (float*)d_out;
    float* out_node  = out;                              // (b, n, 128)
    float* out_coors = out + (size_t)NROWS*DIM;          // (b, n, 3)

    float *G, *H, *Hn;
    cudaGetSymbolAddress((void**)&G,  g_G);
    cudaGetSymbolAddress((void**)&H,  g_H);
    cudaGetSymbolAddress((void**)&Hn, g_Hn);

    // 1) KNN
    knn_kernel<<<dim3(NPTS, BATCH), 256>>>(coors);

    // 2) G = feats @ We1[0:128] + be1 ; H = feats @ We1[128:256]  (ldc = EDIMP)
    dim3 gGH((EDIM + 63)/64, NROWS/64);
    sgemm_kernel<<<gGH, 256>>>(feats, We1,            be1,     nullptr, G, NROWS, EDIM, DIM, 0, EDIMP);
    sgemm_kernel<<<gGH, 256>>>(feats, We1 + 128*EDIM, nullptr, nullptr, H, NROWS, EDIM, DIM, 0, EDIMP);

    // 3) edge kernel (8 warps/block, 1 node/warp, lane = edge)
    cudaFuncSetAttribute(edge_kernel, cudaFuncAttributeMaxDynamicSharedMemorySize, EDGE_SMEM_BYTES);
    edge_kernel<<<dim3(NPTS/8, BATCH), 256, EDGE_SMEM_BYTES>>>(
        coors, We2, be2, Wc1, bc1, Wc2, bc2, We1, out_coors);

    // 4) node MLP (layer 1 fuses [feats | m_i] concat)
    gemm_node1<<<dim3((2*DIM)/64, NROWS/64), 256>>>(feats, Wn1, bn1, Hn, 2*DIM);
    sgemm_kernel<<<dim3(DIM/64, NROWS/64), 256>>>(Hn, Wn2, bn2, feats, out_node, NROWS, DIM, 2*DIM, 0, DIM);
}

// round 11
// speedup vs baseline: 1.6177x; 1.6177x over previous
#include <cuda_runtime.h>
#include <math.h>
#include <float.h>
#include <stdint.h>

#define BATCH 2
#define NPTS  4096
#define DIM   128
#define MD    16
#define KNBR  32
#define EDIM  530              // 2*EDGE_IN
#define EDIMP 544              // padded to 17*32
#define NROWS (BATCH*NPTS)     // 8192

// ---------------- scratch (device globals; zero-initialized at load) ----------------
__device__ float g_G [NROWS*EDIMP];   // padded cols stay zero (never written)
__device__ float g_H [NROWS*EDIMP];
__device__ float g_mi[NROWS*MD];
__device__ float g_Hn[NROWS*(2*DIM)];
__device__ float g_knn_dist[NROWS*KNBR];
__device__ int   g_knn_idx [NROWS*KNBR];

// fast SiLU: MUFU.EX2 + MUFU.RCP, rel err ~1e-6 (threshold is 1e-3)
__device__ __forceinline__ float silu_f(float x){
    return __fdividef(x, 1.0f + __expf(-x));
}

// ---------------- kernel 1: exact KNN ----------------
__global__ __launch_bounds__(256) void knn_kernel(const float* __restrict__ coors)
{
    __shared__ unsigned long long ck[256];
    const int b = blockIdx.y, i = blockIdx.x, tid = threadIdx.x;
    const int lane = tid & 31, w = tid >> 5;
    const float* cb = coors + (size_t)b*NPTS*3;
    const float cx = cb[i*3+0], cy = cb[i*3+1], cz = cb[i*3+2];

    float dl[16];
    const int jbase = w*512 + lane;
    #pragma unroll
    for (int t = 0; t < 16; t++) {
        int j = jbase + t*32;
        float dx = cx - cb[j*3+0];
        float dy = cy - cb[j*3+1];
        float dz = cz - cb[j*3+2];
        dl[t] = __fadd_rn(__fadd_rn(__fmul_rn(dx,dx), __fmul_rn(dy,dy)), __fmul_rn(dz,dz));
    }

    for (int k = 0; k < KNBR; k++) {
        float best = FLT_MAX; int bt = 0;
        #pragma unroll
        for (int t = 0; t < 16; t++)
            if (dl[t] < best) { best = dl[t]; bt = t; }
        int bj = jbase + bt*32;
        float v = best; int jj = (best < FLT_MAX) ? bj : 0x7fffffff;
        #pragma unroll
        for (int off = 16; off > 0; off >>= 1) {
            float v2 = __shfl_xor_sync(0xffffffffu, v, off);
            int   j2 = __shfl_xor_sync(0xffffffffu, jj, off);
            if (v2 < v || (v2 == v && j2 < jj)) { v = v2; jj = j2; }
        }
        if (jj == bj) dl[bt] = FLT_MAX;
        if (lane == 0)
            ck[w*32 + k] = ((unsigned long long)__float_as_uint(v) << 32) | (unsigned int)jj;
    }
    __syncthreads();

    // bitonic sort 256 keys ascending
    #pragma unroll 1
    for (int k = 2; k <= 256; k <<= 1) {
        #pragma unroll 1
        for (int j = k >> 1; j > 0; j >>= 1) {
            int p = tid ^ j;
            if (p > tid) {
                bool asc = ((tid & k) == 0);
                unsigned long long a = ck[tid], bb = ck[p];
                if ((a > bb) == asc) { ck[tid] = bb; ck[p] = a; }
            }
            __syncthreads();
        }
    }
    if (tid < KNBR) {
        unsigned long long key = ck[tid];
        const int gi = b*NPTS + i;
        g_knn_dist[gi*KNBR + tid] = __uint_as_float((unsigned int)(key >> 32));
        g_knn_idx [gi*KNBR + tid] = (int)(unsigned int)(key & 0xffffffffu);
    }
}

// ============ GEMM: 128x64 tile, BK=8, 8x4 per thread, single-buffered ============
// A: M x K row-major (lda); concat mode: A = [feats(DIM) | g_mi(MD)], K = 144.
// B: K x N row-major. Requires M % 128 == 0, K % 8 == 0.
__global__ __launch_bounds__(256) void gemm_fast(
    const float* __restrict__ A, const float* __restrict__ B,
    const float* __restrict__ bias, const float* __restrict__ resid,
    float* __restrict__ C, int M, int N, int K, int lda, int ldc,
    int act, int concat)
{
    __shared__ float As[8][132];   // pitch 132: conflict-free transposed stores
    __shared__ float Bs[8][68];

    const int tid = threadIdx.x;
    const int tx = tid & 15, ty = tid >> 4;
    const int rowBase = blockIdx.y * 128, colBase = blockIdx.x * 64;

    const int arow = tid >> 1;          // 0..127
    const int ak4  = (tid & 1) * 4;     // 0 or 4
    const int bk   = tid >> 5;          // 0..7
    const int bc   = (tid & 31) * 2;    // 0..62

    float acc[8][4] = {};

    #pragma unroll 1
    for (int k0 = 0; k0 < K; k0 += 8) {
        // ---- load tile into registers ----
        float4 a4;
        if (concat) {
            int kk = k0 + ak4;
            if (kk < DIM) a4 = *(const float4*)&A[(size_t)(rowBase + arow)*DIM + kk];
            else          a4 = *(const float4*)&g_mi[(size_t)(rowBase + arow)*MD + (kk - DIM)];
        } else {
            a4 = *(const float4*)&A[(size_t)(rowBase + arow)*lda + k0 + ak4];
        }
        float b0 = 0.0f, b1 = 0.0f;
        {
            int c0 = colBase + bc;
            const float* Brow = B + (size_t)(k0 + bk)*N;
            if (c0     < N) b0 = Brow[c0];
            if (c0 + 1 < N) b1 = Brow[c0 + 1];
        }
        __syncthreads();   // previous iteration's smem reads done
        As[ak4+0][arow] = a4.x; As[ak4+1][arow] = a4.y;
        As[ak4+2][arow] = a4.z; As[ak4+3][arow] = a4.w;
        Bs[bk][bc] = b0; Bs[bk][bc+1] = b1;
        __syncthreads();

        // ---- compute ----
        #pragma unroll
        for (int kk = 0; kk < 8; kk++) {
            float4 a0 = *(const float4*)&As[kk][ty*4];
            float4 a1 = *(const float4*)&As[kk][ty*4 + 64];
            float4 bv = *(const float4*)&Bs[kk][tx*4];
            float ar[8] = {a0.x,a0.y,a0.z,a0.w,a1.x,a1.y,a1.z,a1.w};
            float br[4] = {bv.x,bv.y,bv.z,bv.w};
            #pragma unroll
            for (int i = 0; i < 8; i++)
                #pragma unroll
                for (int j = 0; j < 4; j++)
                    acc[i][j] = fmaf(ar[i], br[j], acc[i][j]);
        }
    }

    // ---- epilogue ----
    #pragma unroll
    for (int i = 0; i < 8; i++) {
        int r = rowBase + ((i < 4) ? (ty*4 + i) : (64 + ty*4 + (i - 4)));
        #pragma unroll
        for (int j = 0; j < 4; j++) {
            int col = colBase + tx*4 + j;
            if (col < N) {
                float v = acc[i][j];
                if (bias)  v += bias[col];
                if (act)   v = silu_f(v);
                if (resid) v += resid[(size_t)r*N + col];
                C[(size_t)r*ldc + col] = v;
            }
        }
    }
}

// ---------------- edge kernel: 8 warps, 1 node/warp, lane = edge ----------------
#define SM_W2    0
#define SM_WF    (16*EDIMP)
#define SM_WC1   (25*EDIMP)
#define SM_BC1   (SM_WC1 + 1024)
#define SM_WC2   (SM_BC1 + 64)
#define SM_BE2   (SM_WC2 + 64)
#define SM_HS    (SM_BE2 + 16)
#define HS_PITCH 36                     // 32 cols + 4 pad
#define HS_WARP  (32*HS_PITCH)          // 1 node x 32 rows x 36
#define SM_TOTAL_FLOATS (SM_HS + 8*HS_WARP)
#define EDGE_SMEM_BYTES (SM_TOTAL_FLOATS * 4)

__global__ __launch_bounds__(256, 2) void edge_kernel(
    const float* __restrict__ coors,
    const float* __restrict__ We2,  const float* __restrict__ be2,
    const float* __restrict__ Wc1,  const float* __restrict__ bc1,
    const float* __restrict__ Wc2,  const float* __restrict__ bc2,
    const float* __restrict__ We1,
    float* __restrict__ out_coors)
{
    extern __shared__ float sm[];
    float* sW2  = sm + SM_W2;    // [16][544]
    float* sWf  = sm + SM_WF;    // [9][544]
    float* sWc1 = sm + SM_WC1;   // [16][64]
    float* sBc1 = sm + SM_BC1;
    float* sWc2 = sm + SM_WC2;
    float* sBe2 = sm + SM_BE2;

    const int tid = threadIdx.x, lane = tid & 31, w = tid >> 5;
    const int b = blockIdx.y;
    const int i = blockIdx.x * 8 + w;
    const int gi = b*NPTS + i;

    // cooperative weight staging (256 threads)
    for (int t = tid; t < 16*EDIMP; t += 256) {
        int m = t / EDIMP, x = t % EDIMP;
        sW2[t] = (x < EDIM) ? We2[x*16 + m] : 0.0f;
    }
    for (int t = tid; t < 9*EDIMP; t += 256) {
        int r = t / EDIMP, x = t % EDIMP;
        sWf[t] = (x < EDIM) ? We1[(256 + r)*EDIM + x] : 0.0f;
    }
    for (int t = tid; t < 1024; t += 256) sWc1[t] = Wc1[t];
    if (tid < 64) { sBc1[tid] = bc1[tid]; sWc2[tid] = Wc2[tid]; }
    if (tid < 16) sBe2[tid] = be2[tid];
    __syncthreads();

    const float bc2v = bc2[0];

    // this lane's edge
    const int   j = g_knn_idx [gi*KNBR + lane];
    const float d = g_knn_dist[gi*KNBR + lane];
    float f[9];
    {
        const float invs[4] = {1.0f, 0.5f, 0.25f, 0.125f};
        #pragma unroll
        for (int r = 0; r < 4; r++) {
            float sv, cv;
            sincosf(d * invs[r], &sv, &cv);
            f[r] = sv; f[4+r] = cv;
        }
        f[8] = d;
    }

    const float* Hb = g_H + (size_t)b*NPTS*EDIMP;
    const float* Gp = g_G + (size_t)gi*EDIMP;
    float* hs = sm + SM_HS + w*HS_WARP;    // [32][36]

    float acc[16] = {};

    const int rr = (lane >> 3);          // row sub-index within 4-row group
    const int cc = (lane & 7) * 4;       // float col offset within chunk

    #pragma unroll 1
    for (int ch = 0; ch < 17; ch++) {
        const int c0 = ch * 32;
        __syncwarp();
        // coalesced staging: instr i loads rows 4i..4i+3, 8 lanes per 128B line
        #pragma unroll
        for (int i2 = 0; i2 < 8; i2++) {
            int row = i2*4 + rr;
            int jr = __shfl_sync(0xffffffffu, j, row);
            float4 v = __ldg((const float4*)(Hb + (size_t)jr*EDIMP + c0 + cc));
            *(float4*)&hs[row*HS_PITCH + cc] = v;
        }
        __syncwarp();
        #pragma unroll
        for (int xs = 0; xs < 8; xs++) {
            const int x = c0 + xs*4;
            float4 g4 = __ldg((const float4*)(Gp + x));       // broadcast
            float4 h4 = *(const float4*)&hs[lane*HS_PITCH + xs*4];
            float t0 = g4.x + h4.x, t1 = g4.y + h4.y, t2 = g4.z + h4.z, t3 = g4.w + h4.w;
            #pragma unroll
            for (int r = 0; r < 9; r++) {
                float4 wf = *(const float4*)&sWf[r*EDIMP + x]; // broadcast LDS
                t0 = fmaf(f[r], wf.x, t0); t1 = fmaf(f[r], wf.y, t1);
                t2 = fmaf(f[r], wf.z, t2); t3 = fmaf(f[r], wf.w, t3);
            }
            float s0 = silu_f(t0), s1 = silu_f(t1), s2 = silu_f(t2), s3 = silu_f(t3);
            #pragma unroll
            for (int m = 0; m < 16; m++) {
                float4 wm = *(const float4*)&sW2[m*EDIMP + x]; // broadcast LDS
                acc[m] = fmaf(s0, wm.x, fmaf(s1, wm.y, fmaf(s2, wm.z, fmaf(s3, wm.w, acc[m]))));
            }
        }
    }

    // ---------------- epilogue ----------------
    float mij[16];
    #pragma unroll
    for (int m = 0; m < 16; m++) mij[m] = silu_f(acc[m] + sBe2[m]);

    // m_i = sum over lanes; lane m writes component m
    #pragma unroll
    for (int m = 0; m < 16; m++) {
        float v = mij[m];
        #pragma unroll
        for (int off = 16; off > 0; off >>= 1)
            v += __shfl_xor_sync(0xffffffffu, v, off);
        if (lane == m) g_mi[(size_t)gi*MD + m] = v;
    }

    // coors MLP per edge: 16 -> 64 (silu) -> 1
    float cw = 0.0f;
    #pragma unroll 4
    for (int hh = 0; hh < 64; hh++) {
        float v = sBc1[hh];
        #pragma unroll
        for (int m = 0; m < 16; m++)
            v = fmaf(mij[m], sWc1[m*64 + hh], v);
        cw = fmaf(silu_f(v), sWc2[hh], cw);
    }
    cw += bc2v;

    // coors_out = sum_e cw_e * (c_i - c_je) + c_i
    {
        const float ci0 = coors[(size_t)gi*3+0];
        const float ci1 = coors[(size_t)gi*3+1];
        const float ci2 = coors[(size_t)gi*3+2];
        const float* cj = coors + ((size_t)b*NPTS + j)*3;
        float rx = cw * (ci0 - cj[0]);
        float ry = cw * (ci1 - cj[1]);
        float rz = cw * (ci2 - cj[2]);
        #pragma unroll
        for (int off = 16; off > 0; off >>= 1) {
            rx += __shfl_xor_sync(0xffffffffu, rx, off);
            ry += __shfl_xor_sync(0xffffffffu, ry, off);
            rz += __shfl_xor_sync(0xffffffffu, rz, off);
        }
        if (lane == 0) {
            out_coors[(size_t)gi*3+0] = rx + ci0;
            out_coors[(size_t)gi*3+1] = ry + ci1;
            out_coors[(size_t)gi*3+2] = rz + ci2;
        }
    }
}

// ---------------- host launcher ----------------
extern "C" void kernel_launch(void* const* d_in, const int* in_sizes, int n_in,
                              void* d_out, int out_size)
{
    const float* feats = (const float*)d_in[0];
    const float* coors = (const float*)d_in[1];
    const float* We1   = (const float*)d_in[2];
    const float* be1   = (const float*)d_in[3];
    const float* We2   = (const float*)d_in[4];
    const float* be2   = (const float*)d_in[5];
    const float* Wc1   = (const float*)d_in[6];
    const float* bc1   = (const float*)d_in[7];
    const float* Wc2   = (const float*)d_in[8];
    const float* bc2   = (const float*)d_in[9];
    const float* Wn1   = (const float*)d_in[10];
    const float* bn1   = (const float*)d_in[11];
    const float* Wn2   = (const float*)d_in[12];
    const float* bn2   = (const float*)d_in[13];

    float* out       = (float*)d_out;
    float* out_node  = out;                              // (b, n, 128)
    float* out_coors = out + (size_t)NROWS*DIM;          // (b, n, 3)

    float *G, *H, *Hn;
    cudaGetSymbolAddress((void**)&G,  g_G);
    cudaGetSymbolAddress((void**)&H,  g_H);
    cudaGetSymbolAddress((void**)&Hn, g_Hn);

    // 1) KNN
    knn_kernel<<<dim3(NPTS, BATCH), 256>>>(coors);

    // 2) G = feats @ We1[0:128] + be1 ; H = feats @ We1[128:256]  (ldc = EDIMP)
    dim3 gGH((EDIM + 63)/64, NROWS/128);
    gemm_fast<<<gGH, 256>>>(feats, We1,            be1,     nullptr, G,
                            NROWS, EDIM, DIM, DIM, EDIMP, 0, 0);
    gemm_fast<<<gGH, 256>>>(feats, We1 + 128*EDIM, nullptr, nullptr, H,
                            NROWS, EDIM, DIM, DIM, EDIMP, 0, 0);

    // 3) edge kernel (8 warps/block, 1 node/warp, lane = edge)
    cudaFuncSetAttribute(edge_kernel, cudaFuncAttributeMaxDynamicSharedMemorySize, EDGE_SMEM_BYTES);
    edge_kernel<<<dim3(NPTS/8, BATCH), 256, EDGE_SMEM_BYTES>>>(
        coors, We2, be2, Wc1, bc1, Wc2, bc2, We1, out_coors);

    // 4) node MLP: layer1 fused concat [feats | m_i] (K=144, silu), layer2 + residual
    gemm_fast<<<dim3((2*DIM)/64, NROWS/128), 256>>>(feats, Wn1, bn1, nullptr, Hn,
                                                    NROWS, 2*DIM, DIM+MD, DIM, 2*DIM, 1, 1);
    gemm_fast<<<dim3(DIM/64, NROWS/128), 256>>>(Hn, Wn2, bn2, feats, out_node,
                                                NROWS, DIM, 2*DIM, 2*DIM, DIM, 0, 0);
}